// round 3
// baseline (speedup 1.0000x reference)
#include <cuda_runtime.h>
#include <cstddef>

#define NN 50000
#define EE 800000
#define DD 64

// ---------------- static device scratch (no allocations allowed) ----------------
__device__ float g_z[(size_t)EE * DD];     // 204.8 MB edge state
__device__ float g_y[NN * DD];
__device__ float g_xbar[NN * DD];
__device__ float g_S[NN * DD];             // S = incT(z), carried across steps
__device__ float g_xk[NN * DD];
__device__ float g_dis[NN];                // deg^-1/2 (deg includes self loop)

__device__ int g_adj_ptr[NN + 1];
__device__ int g_adj_cur[NN];
__device__ int g_adj_col[2 * EE];
__device__ int g_inc_ptr[NN + 1];
__device__ int g_inc_cur[NN];
__device__ int g_inc_eid[2 * EE];          // signed: +(e+1) for r-side, -(e+1) for c-side
__device__ int g_r[EE];
__device__ int g_c[EE];
__device__ int g_cnt_adj[NN];
__device__ int g_cnt_inc[NN];

// ---------------- precompute ----------------
__global__ void kInit(int n) {
    int i = blockIdx.x * blockDim.x + threadIdx.x;
    if (i < n) { g_cnt_adj[i] = 0; g_cnt_inc[i] = 0; }
}

__global__ void kCount(const int* __restrict__ src, const int* __restrict__ dst, int ne) {
    int e = blockIdx.x * blockDim.x + threadIdx.x;
    if (e >= ne) return;
    int s = src[e], d = dst[e];
    int r = s > d ? s : d;
    int c = s > d ? d : s;
    g_r[e] = r; g_c[e] = c;
    atomicAdd(&g_cnt_adj[s], 1);
    atomicAdd(&g_cnt_adj[d], 1);
    atomicAdd(&g_cnt_inc[r], 1);
    atomicAdd(&g_cnt_inc[c], 1);
}

__global__ void kDis(int n) {
    int i = blockIdx.x * blockDim.x + threadIdx.x;
    if (i >= n) return;
    float x = (float)g_cnt_adj[i] + 1.0f;   // degree with self loop
    float r = rsqrtf(x);
    r = r * (1.5f - 0.5f * x * r * r);      // Newton refine to full fp32 accuracy
    g_dis[i] = r;
}

// single-block exclusive scan; which=0 -> adjacency, which=1 -> incidence
__global__ void kScan(int n, int which) {
    __shared__ int s[1024];
    const int* cnt = which ? g_cnt_inc : g_cnt_adj;
    int* ptr = which ? g_inc_ptr : g_adj_ptr;
    int* cur = which ? g_inc_cur : g_adj_cur;
    int t = threadIdx.x;
    int chunk = (n + 1023) >> 10;
    int beg = t * chunk;
    int end = beg + chunk; if (end > n) end = n;
    int sum = 0;
    for (int i = beg; i < end; i++) sum += cnt[i];
    s[t] = sum;
    __syncthreads();
    for (int off = 1; off < 1024; off <<= 1) {
        int v = (t >= off) ? s[t - off] : 0;
        __syncthreads();
        s[t] += v;
        __syncthreads();
    }
    int run = (t > 0) ? s[t - 1] : 0;
    for (int i = beg; i < end; i++) {
        ptr[i] = run; cur[i] = run; run += cnt[i];
    }
    if (t == 0) ptr[n] = s[1023];
}

__global__ void kFill(const int* __restrict__ src, const int* __restrict__ dst, int ne) {
    int e = blockIdx.x * blockDim.x + threadIdx.x;
    if (e >= ne) return;
    int s = src[e], d = dst[e];
    int p = atomicAdd(&g_adj_cur[s], 1); g_adj_col[p] = d;
    p = atomicAdd(&g_adj_cur[d], 1);     g_adj_col[p] = s;
    int r = g_r[e], c = g_c[e];
    p = atomicAdd(&g_inc_cur[r], 1);     g_inc_eid[p] = e + 1;
    p = atomicAdd(&g_inc_cur[c], 1);     g_inc_eid[p] = -(e + 1);
}

// ---------------- main loop kernels (warp per row, float2 per lane) ----------------

// A: y = 0.25*x0 + 0.75*dis[i]*(sum_{col} dis[col]*xk[col] + dis[i]*xk[i])
//    xbar = y - 0.25*S   (S==0 on first iteration)
__global__ __launch_bounds__(256) void kA(const float* __restrict__ x0, int n, int first) {
    int w = (blockIdx.x * 256 + threadIdx.x) >> 5;
    int lane = threadIdx.x & 31;
    if (w >= n) return;
    const float* xk = first ? x0 : g_xk;
    int base = g_adj_ptr[w], end = g_adj_ptr[w + 1];
    int ofs = 2 * lane;
    float ax = 0.f, ay = 0.f;
    for (int e = base; e < end; e++) {
        int col = __ldg(&g_adj_col[e]);
        float wt = __ldg(&g_dis[col]);
        float2 v = *reinterpret_cast<const float2*>(xk + (size_t)col * DD + ofs);
        ax = fmaf(wt, v.x, ax);
        ay = fmaf(wt, v.y, ay);
    }
    float di = g_dis[w];
    float2 vs = *reinterpret_cast<const float2*>(xk + (size_t)w * DD + ofs);
    ax = fmaf(di, vs.x, ax);
    ay = fmaf(di, vs.y, ay);
    float2 h = *reinterpret_cast<const float2*>(x0 + (size_t)w * DD + ofs);
    float2 yv;
    yv.x = 0.25f * h.x + 0.75f * di * ax;
    yv.y = 0.25f * h.y + 0.75f * di * ay;
    *reinterpret_cast<float2*>(g_y + (size_t)w * DD + ofs) = yv;
    float2 xb = yv;
    if (!first) {
        float2 sv = *reinterpret_cast<const float2*>(g_S + (size_t)w * DD + ofs);
        xb.x -= 0.25f * sv.x;
        xb.y -= 0.25f * sv.y;
    }
    *reinterpret_cast<float2*>(g_xbar + (size_t)w * DD + ofs) = xb;
}

// B: z = l21( z + 2*(dis[r]*xbar[r] - dis[c]*xbar[c]) )  (fused, in place)
__global__ __launch_bounds__(256) void kB(int ne, int zero_z) {
    int e = (blockIdx.x * 256 + threadIdx.x) >> 5;
    int lane = threadIdx.x & 31;
    if (e >= ne) return;
    int r = g_r[e], c = g_c[e];
    float ar = __ldg(&g_dis[r]);
    float bc = __ldg(&g_dis[c]);
    int ofs = 2 * lane;
    float2 xr = *reinterpret_cast<const float2*>(g_xbar + (size_t)r * DD + ofs);
    float2 xc = *reinterpret_cast<const float2*>(g_xbar + (size_t)c * DD + ofs);
    float2 zb;
    zb.x = 2.0f * (ar * xr.x - bc * xc.x);
    zb.y = 2.0f * (ar * xr.y - bc * xc.y);
    float* zp = g_z + (size_t)e * DD + ofs;
    if (!zero_z) {
        float2 z0 = *reinterpret_cast<const float2*>(zp);
        zb.x += z0.x; zb.y += z0.y;
    }
    float ns = zb.x * zb.x + zb.y * zb.y;
    #pragma unroll
    for (int o = 16; o > 0; o >>= 1) ns += __shfl_xor_sync(0xffffffffu, ns, o);
    float rn = sqrtf(ns);
    float sc = (rn > 0.0f) ? fminf(rn, 3.0f) / rn : 0.0f;
    float2 zo;
    zo.x = sc * zb.x;
    zo.y = sc * zb.y;
    *reinterpret_cast<float2*>(zp) = zo;
}

// C: S[i] = dis[i] * sum_{signed inc list} z[e];   xk = y - 0.25*S
__global__ __launch_bounds__(256) void kC(float* __restrict__ out, int n, int write_S, int to_out) {
    int w = (blockIdx.x * 256 + threadIdx.x) >> 5;
    int lane = threadIdx.x & 31;
    if (w >= n) return;
    int base = g_inc_ptr[w], end = g_inc_ptr[w + 1];
    int ofs = 2 * lane;
    float ax = 0.f, ay = 0.f;
    for (int idx = base; idx < end; idx++) {
        int se = __ldg(&g_inc_eid[idx]);
        int e = (se < 0 ? -se : se) - 1;
        float2 zv = *reinterpret_cast<const float2*>(g_z + (size_t)e * DD + ofs);
        if (se > 0) { ax += zv.x; ay += zv.y; }
        else        { ax -= zv.x; ay -= zv.y; }
    }
    float di = g_dis[w];
    float sx = di * ax, sy = di * ay;
    if (write_S) {
        float2 sv; sv.x = sx; sv.y = sy;
        *reinterpret_cast<float2*>(g_S + (size_t)w * DD + ofs) = sv;
    }
    float2 yv = *reinterpret_cast<const float2*>(g_y + (size_t)w * DD + ofs);
    float2 xo;
    xo.x = yv.x - 0.25f * sx;
    xo.y = yv.y - 0.25f * sy;
    float* dstp = to_out ? out : g_xk;
    *reinterpret_cast<float2*>(dstp + (size_t)w * DD + ofs) = xo;
}

// ---------------- launch ----------------
extern "C" void kernel_launch(void* const* d_in, const int* in_sizes, int n_in,
                              void* d_out, int out_size) {
    (void)n_in; (void)out_size;
    const float* x0 = (const float*)d_in[0];
    const int* esrc = (const int*)d_in[1];
    const int* edst = (const int*)d_in[2];
    float* out = (float*)d_out;

    int n  = in_sizes[0] / DD;   // 50000
    int ne = in_sizes[1];        // 800000

    const int TB = 256;
    int gN  = (n + TB - 1) / TB;
    int gE  = (ne + TB - 1) / TB;
    int gWN = (n + 7) / 8;       // warp-per-node
    int gWE = (ne + 7) / 8;      // warp-per-edge

    // per-launch CSR build (graph-capturable, deterministic work)
    kInit<<<gN, TB>>>(n);
    kCount<<<gE, TB>>>(esrc, edst, ne);
    kDis<<<gN, TB>>>(n);
    kScan<<<1, 1024>>>(n, 0);
    kScan<<<1, 1024>>>(n, 1);
    kFill<<<gE, TB>>>(esrc, edst, ne);

    const int K = 10;
    for (int k = 0; k < K; k++) {
        kA<<<gWN, TB>>>(x0, n, k == 0);
        kB<<<gWE, TB>>>(ne, k == 0);
        kC<<<gWN, TB>>>(out, n, k < K - 1, k == K - 1);
    }
}

// round 6
// speedup vs baseline: 1.0489x; 1.0489x over previous
#include <cuda_runtime.h>
#include <cstddef>

#define NN 50000
#define EE 800000
#define DD 64

// ---------------- static device scratch (no allocations allowed) ----------------
__device__ float g_zA[(size_t)EE * DD];    // 204.8 MB edge state, buffer A
__device__ float g_zB[(size_t)EE * DD];    // 204.8 MB edge state, buffer B
__device__ float g_y[NN * DD];
__device__ float g_dx[NN * DD];            // dis[i] * xbar[i]  (only form inc_mv needs)
__device__ float g_S[NN * DD];             // S = incT(z), carried across steps
__device__ float g_xk[NN * DD];
__device__ float g_dis[NN];                // deg^-1/2 (deg includes self loop)

__device__ int g_adj_ptr[NN + 1];
__device__ int g_adj_cur[NN];
__device__ int g_adj_col[2 * EE];
__device__ int g_inc_ptr[NN + 1];
__device__ int g_inc_cur[NN];
__device__ int2 g_inc_pk[2 * EE];          // {signed edge id (+/-(e+1)), other endpoint}
__device__ int g_r[EE];
__device__ int g_c[EE];
__device__ int g_cnt_adj[NN];
__device__ int g_cnt_inc[NN];

// ---------------- precompute ----------------
__global__ void kInit(int n) {
    int i = blockIdx.x * blockDim.x + threadIdx.x;
    if (i < n) { g_cnt_adj[i] = 0; g_cnt_inc[i] = 0; }
}

__global__ void kCount(const int* __restrict__ src, const int* __restrict__ dst, int ne) {
    int e = blockIdx.x * blockDim.x + threadIdx.x;
    if (e >= ne) return;
    int s = src[e], d = dst[e];
    int r = s > d ? s : d;
    int c = s > d ? d : s;
    g_r[e] = r; g_c[e] = c;
    atomicAdd(&g_cnt_adj[s], 1);
    atomicAdd(&g_cnt_adj[d], 1);
    atomicAdd(&g_cnt_inc[r], 1);
    atomicAdd(&g_cnt_inc[c], 1);
}

__global__ void kDis(int n) {
    int i = blockIdx.x * blockDim.x + threadIdx.x;
    if (i >= n) return;
    float x = (float)g_cnt_adj[i] + 1.0f;   // degree with self loop
    float r = rsqrtf(x);
    r = r * (1.5f - 0.5f * x * r * r);      // Newton refine to full fp32 accuracy
    g_dis[i] = r;
}

// single launch: 512 threads scan adjacency counts, 512 scan incidence counts
__global__ void kScan2(int n) {
    __shared__ int s[1024];
    int t = threadIdx.x;
    int half = t >> 9;                 // 0 = adj, 1 = inc
    int tt = t & 511;
    const int* cnt = half ? g_cnt_inc : g_cnt_adj;
    int* ptr = half ? g_inc_ptr : g_adj_ptr;
    int* cur = half ? g_inc_cur : g_adj_cur;
    int chunk = (n + 511) >> 9;
    int beg = tt * chunk;
    int end = beg + chunk; if (end > n) end = n;
    if (beg > n) beg = n;
    int sum = 0;
    for (int i = beg; i < end; i++) sum += cnt[i];
    s[t] = sum;
    __syncthreads();
    for (int off = 1; off < 512; off <<= 1) {
        int v = (tt >= off) ? s[t - off] : 0;
        __syncthreads();
        s[t] += v;
        __syncthreads();
    }
    int run = (tt > 0) ? s[t - 1] : 0;
    for (int i = beg; i < end; i++) {
        ptr[i] = run; cur[i] = run; run += cnt[i];
    }
    if (tt == 0) ptr[n] = s[half * 512 + 511];
}

__global__ void kFill(const int* __restrict__ src, const int* __restrict__ dst, int ne) {
    int e = blockIdx.x * blockDim.x + threadIdx.x;
    if (e >= ne) return;
    int s = src[e], d = dst[e];
    int p = atomicAdd(&g_adj_cur[s], 1); g_adj_col[p] = d;
    p = atomicAdd(&g_adj_cur[d], 1);     g_adj_col[p] = s;
    int r = g_r[e], c = g_c[e];
    int2 pk;
    p = atomicAdd(&g_inc_cur[r], 1); pk.x =  (e + 1); pk.y = c; g_inc_pk[p] = pk;
    p = atomicAdd(&g_inc_cur[c], 1); pk.x = -(e + 1); pk.y = r; g_inc_pk[p] = pk;
}

// ---------------- main loop kernels (warp per row, float2 per lane) ----------------

// A: y = 0.25*x0 + 0.75*dis[i]*(adj gather);  xbar = y - 0.25*S (S==0 first iter);
//    stores dx = dis[i]*xbar (the only form the incidence kernel needs)
__global__ __launch_bounds__(256) void kA(const float* __restrict__ x0, int n, int first) {
    int w = (blockIdx.x * 256 + threadIdx.x) >> 5;
    int lane = threadIdx.x & 31;
    if (w >= n) return;
    const float* xk = first ? x0 : g_xk;
    int base = g_adj_ptr[w], end = g_adj_ptr[w + 1];
    int ofs = 2 * lane;
    float ax = 0.f, ay = 0.f;
    for (int e = base; e < end; e++) {
        int col = __ldg(&g_adj_col[e]);
        float wt = __ldg(&g_dis[col]);
        float2 v = *reinterpret_cast<const float2*>(xk + (size_t)col * DD + ofs);
        ax = fmaf(wt, v.x, ax);
        ay = fmaf(wt, v.y, ay);
    }
    float di = g_dis[w];
    float2 vs = *reinterpret_cast<const float2*>(xk + (size_t)w * DD + ofs);
    ax = fmaf(di, vs.x, ax);
    ay = fmaf(di, vs.y, ay);
    float2 h = *reinterpret_cast<const float2*>(x0 + (size_t)w * DD + ofs);
    float2 yv;
    yv.x = 0.25f * h.x + 0.75f * di * ax;
    yv.y = 0.25f * h.y + 0.75f * di * ay;
    *reinterpret_cast<float2*>(g_y + (size_t)w * DD + ofs) = yv;
    float2 xb = yv;
    if (!first) {
        float2 sv = *reinterpret_cast<const float2*>(g_S + (size_t)w * DD + ofs);
        xb.x -= 0.25f * sv.x;
        xb.y -= 0.25f * sv.y;
    }
    float2 dxv;
    dxv.x = di * xb.x;
    dxv.y = di * xb.y;
    *reinterpret_cast<float2*>(g_dx + (size_t)w * DD + ofs) = dxv;
}

// BC (fused): per node w, over its incidence list:
//   z_new[e] = l21proj( z_old[e] + 2*(dx[r] - dx[c]) )   (recomputed at both endpoint visits)
//   S[w] = dis[w] * sum s * z_new ;  r-side visit writes z_new (double-buffered)
//   xk = y - 0.25*S  (to g_xk, or to out on last step)
__global__ __launch_bounds__(256) void kBC(float* __restrict__ out, int n,
                                           int flip, int first, int last) {
    int w = (blockIdx.x * 256 + threadIdx.x) >> 5;
    int lane = threadIdx.x & 31;
    if (w >= n) return;
    const float* __restrict__ zold = flip ? g_zB : g_zA;
    float* __restrict__ znew       = flip ? g_zA : g_zB;
    int base = g_inc_ptr[w], end = g_inc_ptr[w + 1];
    int ofs = 2 * lane;
    float2 dxw = *reinterpret_cast<const float2*>(g_dx + (size_t)w * DD + ofs);
    float sx = 0.f, sy = 0.f;
    for (int idx = base; idx < end; idx++) {
        int2 pk = __ldg(&g_inc_pk[idx]);
        int se = pk.x, o = pk.y;
        int e = (se < 0 ? -se : se) - 1;
        float2 dxo = *reinterpret_cast<const float2*>(g_dx + (size_t)o * DD + ofs);
        float tx = dxw.x - dxo.x;
        float ty = dxw.y - dxo.y;
        if (se < 0) { tx = -tx; ty = -ty; }   // t = dx[r]-dx[c] regardless of side
        float zx, zy;
        if (first) {
            zx = 2.0f * tx; zy = 2.0f * ty;
        } else {
            float2 z0 = *reinterpret_cast<const float2*>(zold + (size_t)e * DD + ofs);
            zx = z0.x + 2.0f * tx;
            zy = z0.y + 2.0f * ty;
        }
        float ns = zx * zx + zy * zy;
        #pragma unroll
        for (int o2 = 16; o2 > 0; o2 >>= 1) ns += __shfl_xor_sync(0xffffffffu, ns, o2);
        float rn = sqrtf(ns);
        float sc = (rn > 0.0f) ? fminf(rn, 3.0f) / rn : 0.0f;
        zx *= sc; zy *= sc;
        if (se > 0) {
            sx += zx; sy += zy;
            if (!last) {
                float2 zo2; zo2.x = zx; zo2.y = zy;
                *reinterpret_cast<float2*>(znew + (size_t)e * DD + ofs) = zo2;
            }
        } else {
            sx -= zx; sy -= zy;
        }
    }
    float di = g_dis[w];
    float Sx = di * sx, Sy = di * sy;
    if (!last) {
        float2 sv; sv.x = Sx; sv.y = Sy;
        *reinterpret_cast<float2*>(g_S + (size_t)w * DD + ofs) = sv;
    }
    float2 yv = *reinterpret_cast<const float2*>(g_y + (size_t)w * DD + ofs);
    float2 xo;
    xo.x = yv.x - 0.25f * Sx;
    xo.y = yv.y - 0.25f * Sy;
    float* dstp = last ? out : g_xk;
    *reinterpret_cast<float2*>(dstp + (size_t)w * DD + ofs) = xo;
}

// ---------------- launch ----------------
extern "C" void kernel_launch(void* const* d_in, const int* in_sizes, int n_in,
                              void* d_out, int out_size) {
    (void)n_in; (void)out_size;
    const float* x0 = (const float*)d_in[0];
    const int* esrc = (const int*)d_in[1];
    const int* edst = (const int*)d_in[2];
    float* out = (float*)d_out;

    int n  = in_sizes[0] / DD;   // 50000
    int ne = in_sizes[1];        // 800000

    const int TB = 256;
    int gN  = (n + TB - 1) / TB;
    int gE  = (ne + TB - 1) / TB;
    int gWN = (n + 7) / 8;       // warp-per-node

    // per-launch CSR build (graph-capturable, deterministic work)
    kInit<<<gN, TB>>>(n);
    kCount<<<gE, TB>>>(esrc, edst, ne);
    kDis<<<gN, TB>>>(n);
    kScan2<<<1, 1024>>>(n);
    kFill<<<gE, TB>>>(esrc, edst, ne);

    const int K = 10;
    for (int k = 0; k < K; k++) {
        kA<<<gWN, TB>>>(x0, n, k == 0);
        // k=0 writes B (flip=0); k=1 reads B writes A (flip=1); alternating
        kBC<<<gWN, TB>>>(out, n, k & 1, k == 0, k == K - 1);
    }
}

// round 7
// speedup vs baseline: 1.3259x; 1.2641x over previous
#include <cuda_runtime.h>
#include <cstddef>

#define NN 50000
#define EE 800000
#define DD 64
#define CH 512

// ---------------- static device scratch (no allocations allowed) ----------------
__device__ float g_z[(size_t)EE * DD];     // 204.8 MB edge state (R-CSR slot order, in-place)
__device__ float g_y[NN * DD];
__device__ float g_dx[NN * DD];            // dis[i] * xbar[i]
__device__ float g_S[NN * DD];             // partial (kR) then final S (kC2), carried to next kA
__device__ float g_xk[NN * DD];
__device__ float g_dis[NN];

__device__ int g_adj_ptr[NN + 1];
__device__ int g_adj_cur[NN];
__device__ int g_adj_col[2 * EE];
__device__ int g_r_ptr[NN + 1];            // edges where node is the max endpoint
__device__ int g_r_cur[NN];
__device__ int g_r_lst[EE];                // other endpoint (c); edge id == slot index
__device__ int g_c_ptr[NN + 1];            // edges where node is the min endpoint
__device__ int g_c_cur[NN];
__device__ int g_c_lst[EE];                // R-slot of that edge
__device__ int g_cnt_adj[NN];
__device__ int g_cnt_r[NN];
__device__ int g_cnt_c[NN];
__device__ int g_part[3 * 128];            // scan partials (3 arrays, <=128 blocks each)

// ---------------- precompute ----------------
__global__ void kInit(int n) {
    int i = blockIdx.x * blockDim.x + threadIdx.x;
    if (i < n) { g_cnt_adj[i] = 0; g_cnt_r[i] = 0; g_cnt_c[i] = 0; }
}

__global__ void kCount(const int* __restrict__ src, const int* __restrict__ dst, int ne) {
    int e = blockIdx.x * blockDim.x + threadIdx.x;
    if (e >= ne) return;
    int s = src[e], d = dst[e];
    int r = s > d ? s : d;
    int c = s > d ? d : s;
    atomicAdd(&g_cnt_adj[s], 1);
    atomicAdd(&g_cnt_adj[d], 1);
    atomicAdd(&g_cnt_r[r], 1);
    atomicAdd(&g_cnt_c[c], 1);
}

__global__ void kDis(int n) {
    int i = blockIdx.x * blockDim.x + threadIdx.x;
    if (i >= n) return;
    float x = (float)g_cnt_adj[i] + 1.0f;   // degree with self loop
    float r = rsqrtf(x);
    r = r * (1.5f - 0.5f * x * r * r);
    g_dis[i] = r;
}

__device__ __forceinline__ const int* cnt_of(int arr) {
    return arr == 0 ? g_cnt_adj : (arr == 1 ? g_cnt_r : g_cnt_c);
}
__device__ __forceinline__ int* ptr_of(int arr) {
    return arr == 0 ? g_adj_ptr : (arr == 1 ? g_r_ptr : g_c_ptr);
}
__device__ __forceinline__ int* cur_of(int arr) {
    return arr == 0 ? g_adj_cur : (arr == 1 ? g_r_cur : g_c_cur);
}

// multi-block scan, stage 1: per-block sums
__global__ void kPart(int n) {
    int arr = blockIdx.y;
    int b = blockIdx.x;
    int t = threadIdx.x;
    int i = b * CH + t;
    __shared__ int s[CH];
    s[t] = (i < n) ? cnt_of(arr)[i] : 0;
    __syncthreads();
    for (int off = CH / 2; off > 0; off >>= 1) {
        if (t < off) s[t] += s[t + off];
        __syncthreads();
    }
    if (t == 0) g_part[arr * 128 + b] = s[0];
}

// stage 2: scan the partials (one block, 3 segments of 128)
__global__ void kScanPart(int n, int nb) {
    __shared__ int s[384];
    int t = threadIdx.x;
    int arr = t >> 7;
    int i = t & 127;
    int v = (i < nb) ? g_part[arr * 128 + i] : 0;
    s[t] = v;
    __syncthreads();
    for (int off = 1; off < 128; off <<= 1) {
        int u = (i >= off) ? s[t - off] : 0;
        __syncthreads();
        s[t] += u;
        __syncthreads();
    }
    g_part[arr * 128 + i] = s[t] - v;      // exclusive prefix of partials
    if (i == nb - 1) ptr_of(arr)[n] = s[t];
}

// stage 3: per-block exclusive scan + offset, write ptr & cur
__global__ void kWrite(int n) {
    int arr = blockIdx.y;
    int b = blockIdx.x;
    int t = threadIdx.x;
    int i = b * CH + t;
    __shared__ int s[CH];
    int v = (i < n) ? cnt_of(arr)[i] : 0;
    s[t] = v;
    __syncthreads();
    for (int off = 1; off < CH; off <<= 1) {
        int u = (t >= off) ? s[t - off] : 0;
        __syncthreads();
        s[t] += u;
        __syncthreads();
    }
    if (i < n) {
        int excl = s[t] - v + g_part[arr * 128 + b];
        ptr_of(arr)[i] = excl;
        cur_of(arr)[i] = excl;
    }
}

__global__ void kFill(const int* __restrict__ src, const int* __restrict__ dst, int ne) {
    int e = blockIdx.x * blockDim.x + threadIdx.x;
    if (e >= ne) return;
    int s = src[e], d = dst[e];
    int p = atomicAdd(&g_adj_cur[s], 1); g_adj_col[p] = d;
    p = atomicAdd(&g_adj_cur[d], 1);     g_adj_col[p] = s;
    int r = s > d ? s : d;
    int c = s > d ? d : s;
    int slot = atomicAdd(&g_r_cur[r], 1);   // edge's new id = its R-CSR slot
    g_r_lst[slot] = c;
    p = atomicAdd(&g_c_cur[c], 1);
    g_c_lst[p] = slot;
}

// ---------------- main loop kernels (warp per row, float2 per lane) ----------------

// A: y = 0.25*x0 + 0.75*dis[i]*(adj gather);  xbar = y - 0.25*S (S==0 first iter);
//    stores dx = dis[i]*xbar
__global__ __launch_bounds__(256) void kA(const float* __restrict__ x0, int n, int first) {
    int w = (blockIdx.x * 256 + threadIdx.x) >> 5;
    int lane = threadIdx.x & 31;
    if (w >= n) return;
    const float* xk = first ? x0 : g_xk;
    int base = g_adj_ptr[w], end = g_adj_ptr[w + 1];
    int ofs = 2 * lane;
    float ax = 0.f, ay = 0.f;
    for (int e = base; e < end; e++) {
        int col = __ldg(&g_adj_col[e]);
        float wt = __ldg(&g_dis[col]);
        float2 v = *reinterpret_cast<const float2*>(xk + (size_t)col * DD + ofs);
        ax = fmaf(wt, v.x, ax);
        ay = fmaf(wt, v.y, ay);
    }
    float di = g_dis[w];
    float2 vs = *reinterpret_cast<const float2*>(xk + (size_t)w * DD + ofs);
    ax = fmaf(di, vs.x, ax);
    ay = fmaf(di, vs.y, ay);
    float2 h = *reinterpret_cast<const float2*>(x0 + (size_t)w * DD + ofs);
    float2 yv;
    yv.x = 0.25f * h.x + 0.75f * di * ax;
    yv.y = 0.25f * h.y + 0.75f * di * ay;
    *reinterpret_cast<float2*>(g_y + (size_t)w * DD + ofs) = yv;
    float2 xb = yv;
    if (!first) {
        float2 sv = *reinterpret_cast<const float2*>(g_S + (size_t)w * DD + ofs);
        xb.x -= 0.25f * sv.x;
        xb.y -= 0.25f * sv.y;
    }
    float2 dxv;
    dxv.x = di * xb.x;
    dxv.y = di * xb.y;
    *reinterpret_cast<float2*>(g_dx + (size_t)w * DD + ofs) = dxv;
}

// R: for each edge slot s owned by node w (w = max endpoint):
//      z[s] = l21proj( z[s] + 2*(dx[w] - dx[other]) )   (in place, SEQUENTIAL z access)
//    accumulate +side partial into g_S (raw sum, scaled in kC2)
__global__ __launch_bounds__(256) void kR(int n, int first) {
    int w = (blockIdx.x * 256 + threadIdx.x) >> 5;
    int lane = threadIdx.x & 31;
    if (w >= n) return;
    int base = g_r_ptr[w], end = g_r_ptr[w + 1];
    int ofs = 2 * lane;
    float2 dxw = *reinterpret_cast<const float2*>(g_dx + (size_t)w * DD + ofs);
    float sx = 0.f, sy = 0.f;
    for (int s = base; s < end; s++) {
        int o = __ldg(&g_r_lst[s]);
        float2 dxo = *reinterpret_cast<const float2*>(g_dx + (size_t)o * DD + ofs);
        float tx = dxw.x - dxo.x;
        float ty = dxw.y - dxo.y;
        float* zp = g_z + (size_t)s * DD + ofs;
        float zx, zy;
        if (first) {
            zx = 2.0f * tx; zy = 2.0f * ty;
        } else {
            float2 z0 = *reinterpret_cast<const float2*>(zp);
            zx = z0.x + 2.0f * tx;
            zy = z0.y + 2.0f * ty;
        }
        float ns = zx * zx + zy * zy;
        #pragma unroll
        for (int o2 = 16; o2 > 0; o2 >>= 1) ns += __shfl_xor_sync(0xffffffffu, ns, o2);
        float rn = sqrtf(ns);
        float sc = (rn > 0.0f) ? fminf(rn, 3.0f) / rn : 0.0f;
        zx *= sc; zy *= sc;
        sx += zx; sy += zy;
        float2 zo; zo.x = zx; zo.y = zy;
        *reinterpret_cast<float2*>(zp) = zo;
    }
    float2 sv; sv.x = sx; sv.y = sy;
    *reinterpret_cast<float2*>(g_S + (size_t)w * DD + ofs) = sv;   // raw partial
}

// C2: gather already-projected z rows for the -side, finalize S and xk
__global__ __launch_bounds__(256) void kC2(float* __restrict__ out, int n, int last) {
    int w = (blockIdx.x * 256 + threadIdx.x) >> 5;
    int lane = threadIdx.x & 31;
    if (w >= n) return;
    int base = g_c_ptr[w], end = g_c_ptr[w + 1];
    int ofs = 2 * lane;
    float sx = 0.f, sy = 0.f;
    for (int idx = base; idx < end; idx++) {
        int s = __ldg(&g_c_lst[idx]);
        float2 zv = *reinterpret_cast<const float2*>(g_z + (size_t)s * DD + ofs);
        sx += zv.x; sy += zv.y;
    }
    float di = g_dis[w];
    float2 pv = *reinterpret_cast<const float2*>(g_S + (size_t)w * DD + ofs);
    float Sx = di * (pv.x - sx);
    float Sy = di * (pv.y - sy);
    if (!last) {
        float2 sv; sv.x = Sx; sv.y = Sy;
        *reinterpret_cast<float2*>(g_S + (size_t)w * DD + ofs) = sv;
    }
    float2 yv = *reinterpret_cast<const float2*>(g_y + (size_t)w * DD + ofs);
    float2 xo;
    xo.x = yv.x - 0.25f * Sx;
    xo.y = yv.y - 0.25f * Sy;
    float* dstp = last ? out : g_xk;
    *reinterpret_cast<float2*>(dstp + (size_t)w * DD + ofs) = xo;
}

// ---------------- launch ----------------
extern "C" void kernel_launch(void* const* d_in, const int* in_sizes, int n_in,
                              void* d_out, int out_size) {
    (void)n_in; (void)out_size;
    const float* x0 = (const float*)d_in[0];
    const int* esrc = (const int*)d_in[1];
    const int* edst = (const int*)d_in[2];
    float* out = (float*)d_out;

    int n  = in_sizes[0] / DD;   // 50000
    int ne = in_sizes[1];        // 800000

    const int TB = 256;
    int gN  = (n + TB - 1) / TB;
    int gE  = (ne + TB - 1) / TB;
    int gWN = (n + 7) / 8;       // warp-per-node
    int nb  = (n + CH - 1) / CH; // scan blocks per array (<=128)

    // per-launch CSR build
    kInit<<<gN, TB>>>(n);
    kCount<<<gE, TB>>>(esrc, edst, ne);
    kDis<<<gN, TB>>>(n);
    kPart<<<dim3(nb, 3), CH>>>(n);
    kScanPart<<<1, 384>>>(n, nb);
    kWrite<<<dim3(nb, 3), CH>>>(n);
    kFill<<<gE, TB>>>(esrc, edst, ne);

    const int K = 10;
    for (int k = 0; k < K; k++) {
        kA<<<gWN, TB>>>(x0, n, k == 0);
        kR<<<gWN, TB>>>(n, k == 0);
        kC2<<<gWN, TB>>>(out, n, k == K - 1);
    }
}

// round 8
// speedup vs baseline: 1.5212x; 1.1474x over previous
#include <cuda_runtime.h>
#include <cstddef>

#define NN 50000
#define EE 800000
#define DD 64
#define CH 512

// ---------------- static device scratch (no allocations allowed) ----------------
__device__ float g_z[(size_t)EE * DD];     // 204.8 MB edge state (R-CSR slot order, in-place)
__device__ float g_y[NN * DD];
__device__ float g_dx[NN * DD];            // dis[i] * xbar[i]
__device__ float g_S[NN * DD];             // partial (kR) then final S (kC2)
__device__ float g_u[NN * DD];             // dis[i] * xk[i]  (pre-scaled state for kA)
__device__ float g_dis[NN];

__device__ int g_adj_ptr[NN + 1];
__device__ int g_adj_cur[NN];
__device__ int g_adj_col[2 * EE];
__device__ int g_r_ptr[NN + 1];            // edges where node is the max endpoint
__device__ int g_r_cur[NN];
__device__ int g_r_lst[EE];                // other endpoint (c); edge id == slot index
__device__ int g_c_ptr[NN + 1];            // edges where node is the min endpoint
__device__ int g_c_cur[NN];
__device__ int g_c_lst[EE];                // R-slot of that edge
__device__ int g_cnt_adj[NN];
__device__ int g_cnt_r[NN];
__device__ int g_cnt_c[NN];
__device__ int g_part[3 * 128];            // scan partials (3 arrays, <=128 blocks each)

// ---------------- precompute ----------------
__global__ void kInit(int n) {
    int i = blockIdx.x * blockDim.x + threadIdx.x;
    if (i < n) { g_cnt_adj[i] = 0; g_cnt_r[i] = 0; g_cnt_c[i] = 0; }
}

__global__ void kCount(const int* __restrict__ src, const int* __restrict__ dst, int ne) {
    int e = blockIdx.x * blockDim.x + threadIdx.x;
    if (e >= ne) return;
    int s = src[e], d = dst[e];
    int r = s > d ? s : d;
    int c = s > d ? d : s;
    atomicAdd(&g_cnt_adj[s], 1);
    atomicAdd(&g_cnt_adj[d], 1);
    atomicAdd(&g_cnt_r[r], 1);
    atomicAdd(&g_cnt_c[c], 1);
}

__global__ void kDis(int n) {
    int i = blockIdx.x * blockDim.x + threadIdx.x;
    if (i >= n) return;
    float x = (float)g_cnt_adj[i] + 1.0f;   // degree with self loop
    float r = rsqrtf(x);
    r = r * (1.5f - 0.5f * x * r * r);
    g_dis[i] = r;
}

__device__ __forceinline__ const int* cnt_of(int arr) {
    return arr == 0 ? g_cnt_adj : (arr == 1 ? g_cnt_r : g_cnt_c);
}
__device__ __forceinline__ int* ptr_of(int arr) {
    return arr == 0 ? g_adj_ptr : (arr == 1 ? g_r_ptr : g_c_ptr);
}
__device__ __forceinline__ int* cur_of(int arr) {
    return arr == 0 ? g_adj_cur : (arr == 1 ? g_r_cur : g_c_cur);
}

// multi-block scan, stage 1: per-block sums
__global__ void kPart(int n) {
    int arr = blockIdx.y;
    int b = blockIdx.x;
    int t = threadIdx.x;
    int i = b * CH + t;
    __shared__ int s[CH];
    s[t] = (i < n) ? cnt_of(arr)[i] : 0;
    __syncthreads();
    for (int off = CH / 2; off > 0; off >>= 1) {
        if (t < off) s[t] += s[t + off];
        __syncthreads();
    }
    if (t == 0) g_part[arr * 128 + b] = s[0];
}

// stage 2: scan the partials (one block, 3 segments of 128)
__global__ void kScanPart(int n, int nb) {
    __shared__ int s[384];
    int t = threadIdx.x;
    int arr = t >> 7;
    int i = t & 127;
    int v = (i < nb) ? g_part[arr * 128 + i] : 0;
    s[t] = v;
    __syncthreads();
    for (int off = 1; off < 128; off <<= 1) {
        int u = (i >= off) ? s[t - off] : 0;
        __syncthreads();
        s[t] += u;
        __syncthreads();
    }
    g_part[arr * 128 + i] = s[t] - v;      // exclusive prefix of partials
    if (i == nb - 1) ptr_of(arr)[n] = s[t];
}

// stage 3: per-block exclusive scan + offset, write ptr & cur
__global__ void kWrite(int n) {
    int arr = blockIdx.y;
    int b = blockIdx.x;
    int t = threadIdx.x;
    int i = b * CH + t;
    __shared__ int s[CH];
    int v = (i < n) ? cnt_of(arr)[i] : 0;
    s[t] = v;
    __syncthreads();
    for (int off = 1; off < CH; off <<= 1) {
        int u = (t >= off) ? s[t - off] : 0;
        __syncthreads();
        s[t] += u;
        __syncthreads();
    }
    if (i < n) {
        int excl = s[t] - v + g_part[arr * 128 + b];
        ptr_of(arr)[i] = excl;
        cur_of(arr)[i] = excl;
    }
}

__global__ void kFill(const int* __restrict__ src, const int* __restrict__ dst, int ne) {
    int e = blockIdx.x * blockDim.x + threadIdx.x;
    if (e >= ne) return;
    int s = src[e], d = dst[e];
    int p = atomicAdd(&g_adj_cur[s], 1); g_adj_col[p] = d;
    p = atomicAdd(&g_adj_cur[d], 1);     g_adj_col[p] = s;
    int r = s > d ? s : d;
    int c = s > d ? d : s;
    int slot = atomicAdd(&g_r_cur[r], 1);   // edge's new id = its R-CSR slot
    g_r_lst[slot] = c;
    p = atomicAdd(&g_c_cur[c], 1);
    g_c_lst[p] = slot;
}

// ---------------- main loop kernels (warp per row, float2 per lane) ----------------

// A: ax = sum_col u[col] + u[w]  (u = dis*xk, pre-scaled; first iter uses dis*x0)
//    y = 0.25*x0 + 0.75*dis[w]*ax;  xbar = y - 0.25*S (S==0 first);  dx = dis[w]*xbar
__global__ __launch_bounds__(256) void kA(const float* __restrict__ x0, int n, int first) {
    int w = (blockIdx.x * 256 + threadIdx.x) >> 5;
    int lane = threadIdx.x & 31;
    if (w >= n) return;
    int base = g_adj_ptr[w], end = g_adj_ptr[w + 1];
    int ofs = 2 * lane;
    float ax = 0.f, ay = 0.f;
    float di = g_dis[w];
    if (first) {
        for (int e = base; e < end; e++) {
            int col = __ldg(&g_adj_col[e]);
            float wt = __ldg(&g_dis[col]);
            float2 v = *reinterpret_cast<const float2*>(x0 + (size_t)col * DD + ofs);
            ax = fmaf(wt, v.x, ax);
            ay = fmaf(wt, v.y, ay);
        }
        float2 vs = *reinterpret_cast<const float2*>(x0 + (size_t)w * DD + ofs);
        ax = fmaf(di, vs.x, ax);
        ay = fmaf(di, vs.y, ay);
    } else {
        for (int e = base; e < end; e++) {
            int col = __ldg(&g_adj_col[e]);
            float2 v = *reinterpret_cast<const float2*>(g_u + (size_t)col * DD + ofs);
            ax += v.x;
            ay += v.y;
        }
        float2 vs = *reinterpret_cast<const float2*>(g_u + (size_t)w * DD + ofs);
        ax += vs.x;
        ay += vs.y;
    }
    float2 h = *reinterpret_cast<const float2*>(x0 + (size_t)w * DD + ofs);
    float2 yv;
    yv.x = 0.25f * h.x + 0.75f * di * ax;
    yv.y = 0.25f * h.y + 0.75f * di * ay;
    *reinterpret_cast<float2*>(g_y + (size_t)w * DD + ofs) = yv;
    float2 xb = yv;
    if (!first) {
        float2 sv = *reinterpret_cast<const float2*>(g_S + (size_t)w * DD + ofs);
        xb.x -= 0.25f * sv.x;
        xb.y -= 0.25f * sv.y;
    }
    float2 dxv;
    dxv.x = di * xb.x;
    dxv.y = di * xb.y;
    *reinterpret_cast<float2*>(g_dx + (size_t)w * DD + ofs) = dxv;
}

// R: for each edge slot s owned by node w (w = max endpoint):
//      z[s] = l21proj( z[s] + 2*(dx[w] - dx[other]) )   (in place, SEQUENTIAL z access)
//    accumulate +side partial into g_S (raw sum, scaled in kC2)
//    Unrolled x2: two independent norm chains in flight; z pair = 512B contiguous.
__global__ __launch_bounds__(256) void kR(int n, int first) {
    int w = (blockIdx.x * 256 + threadIdx.x) >> 5;
    int lane = threadIdx.x & 31;
    if (w >= n) return;
    int base = g_r_ptr[w], end = g_r_ptr[w + 1];
    int ofs = 2 * lane;
    float2 dxw = *reinterpret_cast<const float2*>(g_dx + (size_t)w * DD + ofs);
    float sx = 0.f, sy = 0.f;
    int s = base;
    for (; s + 1 < end; s += 2) {
        int o0 = __ldg(&g_r_lst[s]);
        int o1 = __ldg(&g_r_lst[s + 1]);
        float2 d0 = *reinterpret_cast<const float2*>(g_dx + (size_t)o0 * DD + ofs);
        float2 d1 = *reinterpret_cast<const float2*>(g_dx + (size_t)o1 * DD + ofs);
        float* zp0 = g_z + (size_t)s * DD + ofs;
        float* zp1 = zp0 + DD;
        float z0x = 2.0f * (dxw.x - d0.x), z0y = 2.0f * (dxw.y - d0.y);
        float z1x = 2.0f * (dxw.x - d1.x), z1y = 2.0f * (dxw.y - d1.y);
        if (!first) {
            float2 a = *reinterpret_cast<const float2*>(zp0);
            float2 b = *reinterpret_cast<const float2*>(zp1);
            z0x += a.x; z0y += a.y;
            z1x += b.x; z1y += b.y;
        }
        float n0 = z0x * z0x + z0y * z0y;
        float n1 = z1x * z1x + z1y * z1y;
        #pragma unroll
        for (int o2 = 16; o2 > 0; o2 >>= 1) {
            n0 += __shfl_xor_sync(0xffffffffu, n0, o2);
            n1 += __shfl_xor_sync(0xffffffffu, n1, o2);
        }
        float r0 = sqrtf(n0), r1 = sqrtf(n1);
        float c0 = (r0 > 0.0f) ? fminf(r0, 3.0f) / r0 : 0.0f;
        float c1 = (r1 > 0.0f) ? fminf(r1, 3.0f) / r1 : 0.0f;
        z0x *= c0; z0y *= c0;
        z1x *= c1; z1y *= c1;
        sx += z0x + z1x; sy += z0y + z1y;
        float2 w0; w0.x = z0x; w0.y = z0y;
        float2 w1; w1.x = z1x; w1.y = z1y;
        *reinterpret_cast<float2*>(zp0) = w0;
        *reinterpret_cast<float2*>(zp1) = w1;
    }
    if (s < end) {
        int o = __ldg(&g_r_lst[s]);
        float2 d0 = *reinterpret_cast<const float2*>(g_dx + (size_t)o * DD + ofs);
        float* zp = g_z + (size_t)s * DD + ofs;
        float zx = 2.0f * (dxw.x - d0.x), zy = 2.0f * (dxw.y - d0.y);
        if (!first) {
            float2 a = *reinterpret_cast<const float2*>(zp);
            zx += a.x; zy += a.y;
        }
        float ns = zx * zx + zy * zy;
        #pragma unroll
        for (int o2 = 16; o2 > 0; o2 >>= 1) ns += __shfl_xor_sync(0xffffffffu, ns, o2);
        float rn = sqrtf(ns);
        float sc = (rn > 0.0f) ? fminf(rn, 3.0f) / rn : 0.0f;
        zx *= sc; zy *= sc;
        sx += zx; sy += zy;
        float2 zo; zo.x = zx; zo.y = zy;
        *reinterpret_cast<float2*>(zp) = zo;
    }
    float2 sv; sv.x = sx; sv.y = sy;
    *reinterpret_cast<float2*>(g_S + (size_t)w * DD + ofs) = sv;   // raw partial
}

// C2: gather already-projected z rows for the -side, finalize S, xk, and u=dis*xk
__global__ __launch_bounds__(256) void kC2(float* __restrict__ out, int n, int last) {
    int w = (blockIdx.x * 256 + threadIdx.x) >> 5;
    int lane = threadIdx.x & 31;
    if (w >= n) return;
    int base = g_c_ptr[w], end = g_c_ptr[w + 1];
    int ofs = 2 * lane;
    float sx = 0.f, sy = 0.f;
    for (int idx = base; idx < end; idx++) {
        int s = __ldg(&g_c_lst[idx]);
        float2 zv = *reinterpret_cast<const float2*>(g_z + (size_t)s * DD + ofs);
        sx += zv.x; sy += zv.y;
    }
    float di = g_dis[w];
    float2 pv = *reinterpret_cast<const float2*>(g_S + (size_t)w * DD + ofs);
    float Sx = di * (pv.x - sx);
    float Sy = di * (pv.y - sy);
    float2 yv = *reinterpret_cast<const float2*>(g_y + (size_t)w * DD + ofs);
    float2 xo;
    xo.x = yv.x - 0.25f * Sx;
    xo.y = yv.y - 0.25f * Sy;
    if (last) {
        *reinterpret_cast<float2*>(out + (size_t)w * DD + ofs) = xo;
    } else {
        float2 sv; sv.x = Sx; sv.y = Sy;
        *reinterpret_cast<float2*>(g_S + (size_t)w * DD + ofs) = sv;
        float2 uv;
        uv.x = di * xo.x;
        uv.y = di * xo.y;
        *reinterpret_cast<float2*>(g_u + (size_t)w * DD + ofs) = uv;
    }
}

// ---------------- launch ----------------
extern "C" void kernel_launch(void* const* d_in, const int* in_sizes, int n_in,
                              void* d_out, int out_size) {
    (void)n_in; (void)out_size;
    const float* x0 = (const float*)d_in[0];
    const int* esrc = (const int*)d_in[1];
    const int* edst = (const int*)d_in[2];
    float* out = (float*)d_out;

    int n  = in_sizes[0] / DD;   // 50000
    int ne = in_sizes[1];        // 800000

    const int TB = 256;
    int gN  = (n + TB - 1) / TB;
    int gE  = (ne + TB - 1) / TB;
    int gWN = (n + 7) / 8;       // warp-per-node
    int nb  = (n + CH - 1) / CH; // scan blocks per array (<=128)

    // per-launch CSR build
    kInit<<<gN, TB>>>(n);
    kCount<<<gE, TB>>>(esrc, edst, ne);
    kDis<<<gN, TB>>>(n);
    kPart<<<dim3(nb, 3), CH>>>(n);
    kScanPart<<<1, 384>>>(n, nb);
    kWrite<<<dim3(nb, 3), CH>>>(n);
    kFill<<<gE, TB>>>(esrc, edst, ne);

    const int K = 10;
    for (int k = 0; k < K; k++) {
        kA<<<gWN, TB>>>(x0, n, k == 0);
        kR<<<gWN, TB>>>(n, k == 0);
        kC2<<<gWN, TB>>>(out, n, k == K - 1);
    }
}